// round 3
// baseline (speedup 1.0000x reference)
#include <cuda_runtime.h>

// ---------------- problem constants ----------------
#define N_NODES 4096
#define UNITS   64
#define BATCH   32
#define TSTEPS  12
#define PRELEN  12
#define NC      (BATCH*UNITS)      // 2048 GEMM columns (b*64+u)
#define TB      (TSTEPS*BATCH)     // 384
#define APAD    132                // As row stride: mult of 4 (LDS.128-safe), 2-way store conflicts

// ---------------- scratch (device globals; no allocation allowed) ----------------
__device__ __align__(128) float g_XT[N_NODES*TB];   // X packed: [m, t*32+b]
__device__ __align__(128) float g_AX[N_NODES*TB];   // A_hat @ XT
__device__ __align__(128) float g_S [N_NODES*NC];   // state: [n, b*64+u]
__device__ __align__(128) float g_AS[N_NODES*NC];   // A_hat @ S
__device__ __align__(128) float g_RS[N_NODES*NC];   // r * state
__device__ __align__(128) float g_AR[N_NODES*NC];   // A_hat @ RS
__device__ __align__(128) float g_UG[N_NODES*NC];   // u gate

// ---------------- packed fp32x2 helpers (Blackwell FFMA2) ----------------
__device__ __forceinline__ unsigned long long pk2(float x, float y) {
    unsigned long long r;
    asm("mov.b64 %0, {%1, %2};" : "=l"(r)
        : "r"(__float_as_uint(x)), "r"(__float_as_uint(y)));
    return r;
}
__device__ __forceinline__ void ffma2(unsigned long long &d,
                                      unsigned long long a,
                                      unsigned long long b) {
    asm("fma.rn.f32x2 %0, %1, %2, %0;" : "+l"(d) : "l"(a), "l"(b));
}
__device__ __forceinline__ float2 unpk(unsigned long long v) {
    unsigned int lo, hi;
    asm("mov.b64 {%0, %1}, %2;" : "=r"(lo), "=r"(hi) : "l"(v));
    return make_float2(__uint_as_float(lo), __uint_as_float(hi));
}

// ---------------- SGEMM: C[M=4096, ncols] = A[4096,4096] @ B[4096, ncols] ----------------
// 128x128 tile, BK=16, 256 threads, 8x8 microtile held as f32x2 pairs, double-buffered smem.
__global__ __launch_bounds__(256, 2)
void sgemm_kernel(float* __restrict__ C, const float* __restrict__ A,
                  const float* __restrict__ B, int ncols) {
    __shared__ float As[2][16 * APAD]; // transposed: [k][m], stride APAD
    __shared__ float Bs[2][16][128];   // [k][n]

    const int tid  = threadIdx.x;
    const int tx   = tid & 15;         // output col group (8 cols)
    const int ty   = tid >> 4;         // output row group (8 rows)
    const int aRow = tid >> 2;         // 0..63  (loads rows aRow, aRow+64)
    const int aCol = (tid & 3) << 2;   // 0,4,8,12
    const int bRow = tid >> 5;         // 0..7   (loads rows bRow, bRow+8)
    const int bCol = (tid & 31) << 2;  // 0..124

    const float* Ap = A + (blockIdx.y * 128 + aRow) * 4096 + aCol;
    const float* Bp = B + blockIdx.x * 128 + bRow * ncols + bCol;

    unsigned long long acc[8][4];
#pragma unroll
    for (int i = 0; i < 8; ++i)
#pragma unroll
        for (int j = 0; j < 4; ++j) acc[i][j] = 0ull;

    // preload tile 0
    {
        float4 a0 = *(const float4*)(Ap);
        float4 a1 = *(const float4*)(Ap + 64 * 4096);
        float4 b0 = *(const float4*)(Bp);
        float4 b1 = *(const float4*)(Bp + 8 * ncols);
        As[0][(aCol + 0) * APAD + aRow] = a0.x; As[0][(aCol + 1) * APAD + aRow] = a0.y;
        As[0][(aCol + 2) * APAD + aRow] = a0.z; As[0][(aCol + 3) * APAD + aRow] = a0.w;
        As[0][(aCol + 0) * APAD + aRow + 64] = a1.x; As[0][(aCol + 1) * APAD + aRow + 64] = a1.y;
        As[0][(aCol + 2) * APAD + aRow + 64] = a1.z; As[0][(aCol + 3) * APAD + aRow + 64] = a1.w;
        *(float4*)&Bs[0][bRow][bCol]     = b0;
        *(float4*)&Bs[0][bRow + 8][bCol] = b1;
    }
    __syncthreads();

#pragma unroll 1
    for (int kt = 0; kt < 256; ++kt) {
        const int buf = kt & 1;
        float4 na0, na1, nb0, nb1;
        if (kt < 255) {  // prefetch next K-tile into registers
            na0 = *(const float4*)(Ap + (kt + 1) * 16);
            na1 = *(const float4*)(Ap + 64 * 4096 + (kt + 1) * 16);
            nb0 = *(const float4*)(Bp + (kt + 1) * 16 * ncols);
            nb1 = *(const float4*)(Bp + ((kt + 1) * 16 + 8) * ncols);
        }
#pragma unroll
        for (int k = 0; k < 16; ++k) {
            float4 a0 = *(const float4*)&As[buf][k * APAD + ty * 8];
            float4 a1 = *(const float4*)&As[buf][k * APAD + ty * 8 + 4];
            float4 b0 = *(const float4*)&Bs[buf][k][tx * 8];
            float4 b1 = *(const float4*)&Bs[buf][k][tx * 8 + 4];
            unsigned long long bp0 = pk2(b0.x, b0.y);
            unsigned long long bp1 = pk2(b0.z, b0.w);
            unsigned long long bp2 = pk2(b1.x, b1.y);
            unsigned long long bp3 = pk2(b1.z, b1.w);
            float av[8] = {a0.x, a0.y, a0.z, a0.w, a1.x, a1.y, a1.z, a1.w};
#pragma unroll
            for (int i = 0; i < 8; ++i) {
                unsigned long long ai = pk2(av[i], av[i]);
                ffma2(acc[i][0], ai, bp0);
                ffma2(acc[i][1], ai, bp1);
                ffma2(acc[i][2], ai, bp2);
                ffma2(acc[i][3], ai, bp3);
            }
        }
        if (kt < 255) {
            const int nbuf = buf ^ 1;
            __syncthreads();
            As[nbuf][(aCol + 0) * APAD + aRow] = na0.x; As[nbuf][(aCol + 1) * APAD + aRow] = na0.y;
            As[nbuf][(aCol + 2) * APAD + aRow] = na0.z; As[nbuf][(aCol + 3) * APAD + aRow] = na0.w;
            As[nbuf][(aCol + 0) * APAD + aRow + 64] = na1.x; As[nbuf][(aCol + 1) * APAD + aRow + 64] = na1.y;
            As[nbuf][(aCol + 2) * APAD + aRow + 64] = na1.z; As[nbuf][(aCol + 3) * APAD + aRow + 64] = na1.w;
            *(float4*)&Bs[nbuf][bRow][bCol]     = nb0;
            *(float4*)&Bs[nbuf][bRow + 8][bCol] = nb1;
            __syncthreads();
        }
    }

    float* Cp = C + (blockIdx.y * 128 + ty * 8) * ncols + blockIdx.x * 128 + tx * 8;
#pragma unroll
    for (int i = 0; i < 8; ++i) {
        float2 p0 = unpk(acc[i][0]), p1 = unpk(acc[i][1]);
        float2 p2 = unpk(acc[i][2]), p3 = unpk(acc[i][3]);
        float4 v0 = make_float4(p0.x, p0.y, p1.x, p1.y);
        float4 v1 = make_float4(p2.x, p2.y, p3.x, p3.y);
        *(float4*)(Cp + i * ncols)     = v0;
        *(float4*)(Cp + i * ncols + 4) = v1;
    }
}

// ---------------- input packing ----------------
__global__ void pack_xt_kernel(const float* __restrict__ X) {
    int i = blockIdx.x * blockDim.x + threadIdx.x;  // over T*B*N
    if (i < TSTEPS * BATCH * N_NODES) {
        int m  = i & (N_NODES - 1);
        int tb = i >> 12;               // t*32 + b
        g_XT[m * TB + tb] = X[i];
    }
}
__global__ void pack_s_kernel(const float* __restrict__ st) {
    int i = blockIdx.x * blockDim.x + threadIdx.x;  // over B*N*U
    if (i < BATCH * N_NODES * UNITS) {
        int u = i & 63;
        int n = (i >> 6) & (N_NODES - 1);
        int b = i >> 18;
        g_S[n * NC + b * UNITS + u] = st[i];
    }
}

// ---------------- gate 1: v1 = sigmoid(gc1); scatter r*state -> RS, u -> UG ----------------
// TGCN chunk(2,dim=1) quirk on flattened (N,2U):
//   v1[b,n,j] is r for node 2n+(j>>6), unit j&63   when n < 2048
//   v1[b,n,j] is u for node 2(n-2048)+(j>>6)       when n >= 2048
__global__ __launch_bounds__(128)
void gates1_kernel(const float* __restrict__ W1, const float* __restrict__ b1, int t) {
    __shared__ float asr[16][64];
    __shared__ float axs[16];
    const int j  = threadIdx.x;          // 0..127 output feature
    const int n  = blockIdx.y;           // v1 node
    const int b0 = blockIdx.x * 16;      // batch block
    float w[65];
#pragma unroll
    for (int f = 0; f < 65; ++f) w[f] = W1[f * 128 + j];
    const float bias = b1[j];

    const float* src = g_AS + n * NC + b0 * UNITS;
    for (int idx = j; idx < 1024; idx += 128) ((float*)asr)[idx] = src[idx];
    if (j < 16) axs[j] = g_AX[n * TB + t * BATCH + b0 + j];
    __syncthreads();

    const int jh = j >> 6, u2 = j & 63;
    for (int p = 0; p < 16; ++p) {
        float acc = bias + axs[p] * w[0];
#pragma unroll
        for (int u = 0; u < 64; ++u) acc += asr[p][u] * w[u + 1];
        float sg = 1.f / (1.f + __expf(-acc));
        const int b = b0 + p;
        if (n < 2048) {
            const int idx = (2 * n + jh) * NC + b * UNITS + u2;
            g_RS[idx] = sg * g_S[idx];
        } else {
            g_UG[(2 * (n - 2048) + jh) * NC + b * UNITS + u2] = sg;
        }
    }
}

// ---------------- gate 2: c = tanh(gc2); state = u*state + (1-u)*c ----------------
__global__ __launch_bounds__(128)
void gates2_kernel(const float* __restrict__ W2, const float* __restrict__ b2, int t) {
    __shared__ float arr[16][64];
    __shared__ float axs[16];
    const int j  = threadIdx.x;
    const int n  = blockIdx.y;           // real node
    const int b0 = blockIdx.x * 16;
    const int u2 = j & 63, ph = j >> 6;
    float w[65];
#pragma unroll
    for (int f = 0; f < 65; ++f) w[f] = W2[f * 64 + u2];
    const float bias = b2[u2];

    const float* src = g_AR + n * NC + b0 * UNITS;
    for (int idx = j; idx < 1024; idx += 128) ((float*)arr)[idx] = src[idx];
    if (j < 16) axs[j] = g_AX[n * TB + t * BATCH + b0 + j];
    __syncthreads();

    for (int pp = 0; pp < 8; ++pp) {
        const int p = pp * 2 + ph;
        const int b = b0 + p;
        float acc = bias + axs[p] * w[0];
#pragma unroll
        for (int u = 0; u < 64; ++u) acc += arr[p][u] * w[u + 1];
        float c = tanhf(acc);
        const int idx = n * NC + b * UNITS + u2;
        const float ug = g_UG[idx];
        g_S[idx] = ug * g_S[idx] + (1.f - ug) * c;
    }
}

// ---------------- output head: out[b,p,n] = state[b,n,:] @ Wo + bo ----------------
__global__ __launch_bounds__(128)
void final_kernel(const float* __restrict__ Wo, const float* __restrict__ bo,
                  float* __restrict__ out) {
    __shared__ float srow[NC];
    __shared__ float wo[UNITS * PRELEN];
    __shared__ float bos[PRELEN];
    const int n = blockIdx.x, j = threadIdx.x;
    for (int idx = j; idx < NC; idx += 128) srow[idx] = g_S[n * NC + idx];
    for (int idx = j; idx < UNITS * PRELEN; idx += 128) wo[idx] = Wo[idx];
    if (j < PRELEN) bos[j] = bo[j];
    __syncthreads();
    for (int o = j; o < BATCH * PRELEN; o += 128) {
        int b = o / PRELEN, p = o - b * PRELEN;
        float acc = bos[p];
#pragma unroll
        for (int u = 0; u < UNITS; ++u) acc += srow[b * UNITS + u] * wo[u * PRELEN + p];
        out[b * (PRELEN * N_NODES) + p * N_NODES + n] = acc;
    }
}

// ---------------- launch ----------------
extern "C" void kernel_launch(void* const* d_in, const int* in_sizes, int n_in,
                              void* d_out, int out_size) {
    const float* A  = (const float*)d_in[0];
    const float* X  = (const float*)d_in[1];
    const float* st = (const float*)d_in[2];
    const float* W1 = (const float*)d_in[3];
    const float* b1 = (const float*)d_in[4];
    const float* W2 = (const float*)d_in[5];
    const float* b2 = (const float*)d_in[6];
    const float* Wo = (const float*)d_in[7];
    const float* bo = (const float*)d_in[8];
    float* out = (float*)d_out;
    (void)in_sizes; (void)n_in; (void)out_size;

    float *pXT, *pAX, *pS, *pAS, *pRS, *pAR;
    cudaGetSymbolAddress((void**)&pXT, g_XT);
    cudaGetSymbolAddress((void**)&pAX, g_AX);
    cudaGetSymbolAddress((void**)&pS,  g_S);
    cudaGetSymbolAddress((void**)&pAS, g_AS);
    cudaGetSymbolAddress((void**)&pRS, g_RS);
    cudaGetSymbolAddress((void**)&pAR, g_AR);

    pack_xt_kernel<<<(TSTEPS * BATCH * N_NODES + 255) / 256, 256>>>(X);
    pack_s_kernel<<<(BATCH * N_NODES * UNITS + 255) / 256, 256>>>(st);
    // AX = A_hat @ XT for all timesteps at once
    sgemm_kernel<<<dim3(TB / 128, 32), 256>>>(pAX, A, pXT, TB);

    for (int t = 0; t < TSTEPS; ++t) {
        sgemm_kernel<<<dim3(NC / 128, 32), 256>>>(pAS, A, pS, NC);   // A @ state
        gates1_kernel<<<dim3(2, N_NODES), 128>>>(W1, b1, t);          // r,u gates; RS, UG
        sgemm_kernel<<<dim3(NC / 128, 32), 256>>>(pAR, A, pRS, NC);  // A @ (r*state)
        gates2_kernel<<<dim3(2, N_NODES), 128>>>(W2, b2, t);          // c; state update
    }

    final_kernel<<<N_NODES, 128>>>(Wo, bo, out);
}

// round 5
// speedup vs baseline: 2.0975x; 2.0975x over previous
#include <cuda_runtime.h>
#include <cuda_bf16.h>
#include <cstdint>

// ---------------- problem constants ----------------
#define N_NODES 4096
#define UNITS   64
#define BATCH   32
#define TSTEPS  12
#define PRELEN  12
#define NC      2048                 // GEMM columns for state (b*64+u)
#define TB      384                  // t*32+b columns for X
#define A_PART  ((size_t)N_NODES * N_NODES)

// ---------------- scratch (device globals; no allocation allowed) ----------------
__device__ __align__(128) float g_S [N_NODES*NC];   // state fp32 [node][col]
__device__ __align__(128) float g_AS[N_NODES*NC];   // A @ S
__device__ __align__(128) float g_RS[N_NODES*NC];   // r * state
__device__ __align__(128) float g_AR[N_NODES*NC];   // A @ RS
__device__ __align__(128) float g_UG[N_NODES*NC];   // u gate
__device__ __align__(128) float g_AX[N_NODES*TB];   // A @ X (all steps)
__device__ __align__(128) __nv_bfloat16 g_Abf[2*A_PART];             // A hi|lo, [m][k]
__device__ __align__(128) __nv_bfloat16 g_Sbf[2*(size_t)NC*N_NODES]; // S hi|lo, [n][k]
__device__ __align__(128) __nv_bfloat16 g_Rbf[2*(size_t)NC*N_NODES]; // RS hi|lo, [n][k]
__device__ __align__(128) __nv_bfloat16 g_Xbf[2*(size_t)TB*N_NODES]; // X hi|lo, [tb][k]

// ---------------- PTX helpers (all baseline-PTX, sm_80+) ----------------
__device__ __forceinline__ uint32_t s2u(const void* p) {
    uint32_t a;
    asm("{ .reg .u64 t; cvta.to.shared.u64 t, %1; cvt.u32.u64 %0, t; }" : "=r"(a) : "l"(p));
    return a;
}
__device__ __forceinline__ void cp16(uint32_t dst, const void* src) {
    asm volatile("cp.async.cg.shared.global [%0], [%1], 16;" :: "r"(dst), "l"(src) : "memory");
}
__device__ __forceinline__ void cp_commit() {
    asm volatile("cp.async.commit_group;" ::: "memory");
}
template<int N>
__device__ __forceinline__ void cp_wait() {
    asm volatile("cp.async.wait_group %0;" :: "n"(N) : "memory");
}
__device__ __forceinline__ void ldm_x4(uint32_t* r, uint32_t a) {
    asm volatile("ldmatrix.sync.aligned.m8n8.x4.shared.b16 {%0,%1,%2,%3}, [%4];"
                 : "=r"(r[0]), "=r"(r[1]), "=r"(r[2]), "=r"(r[3]) : "r"(a));
}
__device__ __forceinline__ void ldm_x2(uint32_t* r, uint32_t a) {
    asm volatile("ldmatrix.sync.aligned.m8n8.x2.shared.b16 {%0,%1}, [%2];"
                 : "=r"(r[0]), "=r"(r[1]) : "r"(a));
}
__device__ __forceinline__ void mma_bf16(float* d, const uint32_t* a, const uint32_t* b) {
    asm volatile(
        "mma.sync.aligned.m16n8k16.row.col.f32.bf16.bf16.f32 "
        "{%0,%1,%2,%3}, {%4,%5,%6,%7}, {%8,%9}, {%0,%1,%2,%3};"
        : "+f"(d[0]), "+f"(d[1]), "+f"(d[2]), "+f"(d[3])
        : "r"(a[0]), "r"(a[1]), "r"(a[2]), "r"(a[3]), "r"(b[0]), "r"(b[1]));
}

// ---------------- HMMA split-GEMM ----------------
// C[m, n] = sum_k A[m,k]*B[n,k] in (emulated) fp32 via bf16 hi/lo 3 products.
// CTA tile 128x128, BK=32, 256 threads, warp tile 64x32, cp.async double buffer.
// Stage layout (bf16, row stride 40 elems = 80B): Ah[128][40] Al Bh Bl.
#define ROWB   80u        // bytes per smem row
#define ARRB   10240u     // bytes per operand array (128*80)
#define STGB   40960u     // bytes per stage
#define NKT    (N_NODES/32)

__global__ __launch_bounds__(256, 2)
void hmma_gemm(float* __restrict__ C, const __nv_bfloat16* __restrict__ Ab,
               const __nv_bfloat16* __restrict__ Bb, int ncols, size_t bPart) {
    extern __shared__ __align__(128) char smem[];
    const uint32_t sm0 = s2u(smem);

    const int tid = threadIdx.x;
    const int lane = tid & 31, wid = tid >> 5;
    const int wm = wid & 1, wn = wid >> 1;          // warp grid 2(m) x 4(n)
    const int m0 = blockIdx.y * 128;
    const int n0 = blockIdx.x * 128;

    float acc[4][4][4];
#pragma unroll
    for (int i = 0; i < 4; ++i)
#pragma unroll
        for (int j = 0; j < 4; ++j)
#pragma unroll
            for (int q = 0; q < 4; ++q) acc[i][j][q] = 0.f;

    auto load_stage = [&](int kt) {
        const uint32_t sb = sm0 + (uint32_t)(kt & 1) * STGB;
        const size_t k0 = (size_t)kt * 32;
#pragma unroll
        for (int it = 0; it < 8; ++it) {
            const int i = tid + it * 256;           // 0..2047 16B-chunks
            const int chunk = i & 3;
            const int row = (i >> 2) & 127;
            const int arr = i >> 9;                 // 0:Ah 1:Al 2:Bh 3:Bl
            const __nv_bfloat16* src =
                (arr < 2)
                    ? Ab + (size_t)arr * A_PART + (size_t)(m0 + row) * N_NODES + k0 + chunk * 8
                    : Bb + (size_t)(arr - 2) * bPart + (size_t)(n0 + row) * N_NODES + k0 + chunk * 8;
            cp16(sb + (uint32_t)arr * ARRB + (uint32_t)row * ROWB + (uint32_t)chunk * 16u, src);
        }
        cp_commit();
    };

    load_stage(0);

#pragma unroll 1
    for (int kt = 0; kt < NKT; ++kt) {
        if (kt + 1 < NKT) { load_stage(kt + 1); cp_wait<1>(); }
        else              { cp_wait<0>(); }
        __syncthreads();

        const uint32_t sb = sm0 + (uint32_t)(kt & 1) * STGB;
        const uint32_t aRowBase = sb + (uint32_t)(wm * 64 + (lane & 15)) * ROWB
                                + (uint32_t)((lane >> 4) << 4);          // +8 bf16 = 16B
        const uint32_t bRowBase = sb + 2u * ARRB
                                + (uint32_t)(wn * 32 + (lane & 7)) * ROWB
                                + (uint32_t)(((lane >> 3) & 1) << 4);
#pragma unroll
        for (int ks = 0; ks < 2; ++ks) {
            const uint32_t kb = (uint32_t)(ks * 32);                      // 16 bf16 = 32B
            uint32_t bh[4][2], bl[4][2];
#pragma unroll
            for (int nf = 0; nf < 4; ++nf) {
                const uint32_t ba = bRowBase + (uint32_t)(nf * 8) * ROWB + kb;
                ldm_x2(bh[nf], ba);
                ldm_x2(bl[nf], ba + ARRB);
            }
#pragma unroll
            for (int mf = 0; mf < 4; ++mf) {
                const uint32_t aa = aRowBase + (uint32_t)(mf * 16) * ROWB + kb;
                uint32_t ah[4], al[4];
                ldm_x4(ah, aa);
                ldm_x4(al, aa + ARRB);
#pragma unroll
                for (int nf = 0; nf < 4; ++nf) {
                    mma_bf16(acc[mf][nf], ah, bh[nf]);
                    mma_bf16(acc[mf][nf], ah, bl[nf]);
                    mma_bf16(acc[mf][nf], al, bh[nf]);
                }
            }
        }
        __syncthreads();
    }

    // epilogue: c frag -> C.  thread holds c[row=grp][col=tl*2,+1] (r0,r1), row+8 (r2,r3)
    const int grp = lane >> 2, tl = lane & 3;
#pragma unroll
    for (int mf = 0; mf < 4; ++mf) {
#pragma unroll
        for (int nf = 0; nf < 4; ++nf) {
            const int row = m0 + wm * 64 + mf * 16 + grp;
            const int col = n0 + wn * 32 + nf * 8 + tl * 2;
            float* p0 = C + (size_t)row * ncols + col;
            p0[0] = acc[mf][nf][0]; p0[1] = acc[mf][nf][1];
            float* p1 = C + (size_t)(row + 8) * ncols + col;
            p1[0] = acc[mf][nf][2]; p1[1] = acc[mf][nf][3];
        }
    }
}

// ---------------- hi/lo split (no transpose): A_hat and X ----------------
__global__ void split_kernel(const float* __restrict__ in, __nv_bfloat16* __restrict__ out,
                             int n, size_t ps) {
    int i = blockIdx.x * blockDim.x + threadIdx.x;
    if (i < n) {
        float v = in[i];
        __nv_bfloat16 h = __float2bfloat16(v);
        out[i] = h;
        out[ps + i] = __float2bfloat16(v - __bfloat162float(h));
    }
}

// ---------------- transpose + hi/lo split: fp32 [node][col] -> bf16 [col][node] ----------------
__global__ __launch_bounds__(256)
void splitT_kernel(const float* __restrict__ in, __nv_bfloat16* __restrict__ out) {
    __shared__ float tile[32][33];
    const int col0 = blockIdx.x * 32, node0 = blockIdx.y * 32;
    const int tx = threadIdx.x, ty = threadIdx.y;
#pragma unroll
    for (int j = 0; j < 32; j += 8)
        tile[ty + j][tx] = in[(size_t)(node0 + ty + j) * NC + col0 + tx];
    __syncthreads();
#pragma unroll
    for (int j = 0; j < 32; j += 8) {
        float v = tile[tx][ty + j];
        __nv_bfloat16 h = __float2bfloat16(v);
        __nv_bfloat16 l = __float2bfloat16(v - __bfloat162float(h));
        size_t o = (size_t)(col0 + ty + j) * N_NODES + node0 + tx;
        out[o] = h;
        out[(size_t)NC * N_NODES + o] = l;
    }
}

// ---------------- input packing: state -> [node][col] fp32 ----------------
__global__ void pack_s_kernel(const float* __restrict__ st) {
    int i = blockIdx.x * blockDim.x + threadIdx.x;  // over B*N*U
    if (i < BATCH * N_NODES * UNITS) {
        int u = i & 63;
        int n = (i >> 6) & (N_NODES - 1);
        int b = i >> 18;
        g_S[n * NC + b * UNITS + u] = st[i];
    }
}

// ---------------- gate 1: v1 = sigmoid(gc1); scatter r*state -> RS, u -> UG ----------------
// TGCN chunk(2,dim=1) quirk on flattened (N,2U):
//   v1[b,n,j] is r for node 2n+(j>>6), unit j&63   when n < 2048
//   v1[b,n,j] is u for node 2(n-2048)+(j>>6)       when n >= 2048
__global__ __launch_bounds__(128)
void gates1_kernel(const float* __restrict__ W1, const float* __restrict__ b1, int t) {
    __shared__ float asr[16][64];
    __shared__ float axs[16];
    const int j  = threadIdx.x;          // 0..127 output feature
    const int n  = blockIdx.y;           // v1 node
    const int b0 = blockIdx.x * 16;      // batch block
    float w[65];
#pragma unroll
    for (int f = 0; f < 65; ++f) w[f] = W1[f * 128 + j];
    const float bias = b1[j];

    const float* src = g_AS + n * NC + b0 * UNITS;
    for (int idx = j; idx < 1024; idx += 128) ((float*)asr)[idx] = src[idx];
    if (j < 16) axs[j] = g_AX[n * TB + t * BATCH + b0 + j];
    __syncthreads();

    const int jh = j >> 6, u2 = j & 63;
    for (int p = 0; p < 16; ++p) {
        float acc = bias + axs[p] * w[0];
#pragma unroll
        for (int u = 0; u < 64; ++u) acc += asr[p][u] * w[u + 1];
        float sg = 1.f / (1.f + __expf(-acc));
        const int b = b0 + p;
        if (n < 2048) {
            const int idx = (2 * n + jh) * NC + b * UNITS + u2;
            g_RS[idx] = sg * g_S[idx];
        } else {
            g_UG[(2 * (n - 2048) + jh) * NC + b * UNITS + u2] = sg;
        }
    }
}

// ---------------- gate 2: c = tanh(gc2); state = u*state + (1-u)*c ----------------
__global__ __launch_bounds__(128)
void gates2_kernel(const float* __restrict__ W2, const float* __restrict__ b2, int t) {
    __shared__ float arr[16][64];
    __shared__ float axs[16];
    const int j  = threadIdx.x;
    const int n  = blockIdx.y;           // real node
    const int b0 = blockIdx.x * 16;
    const int u2 = j & 63, ph = j >> 6;
    float w[65];
#pragma unroll
    for (int f = 0; f < 65; ++f) w[f] = W2[f * 64 + u2];
    const float bias = b2[u2];

    const float* src = g_AR + n * NC + b0 * UNITS;
    for (int idx = j; idx < 1024; idx += 128) ((float*)arr)[idx] = src[idx];
    if (j < 16) axs[j] = g_AX[n * TB + t * BATCH + b0 + j];
    __syncthreads();

    for (int pp = 0; pp < 8; ++pp) {
        const int p = pp * 2 + ph;
        const int b = b0 + p;
        float acc = bias + axs[p] * w[0];
#pragma unroll
        for (int u = 0; u < 64; ++u) acc += arr[p][u] * w[u + 1];
        float c = tanhf(acc);
        const int idx = n * NC + b * UNITS + u2;
        const float ug = g_UG[idx];
        g_S[idx] = ug * g_S[idx] + (1.f - ug) * c;
    }
}

// ---------------- output head: out[b,p,n] = state[b,n,:] @ Wo + bo ----------------
__global__ __launch_bounds__(128)
void final_kernel(const float* __restrict__ Wo, const float* __restrict__ bo,
                  float* __restrict__ out) {
    __shared__ float srow[NC];
    __shared__ float wo[UNITS * PRELEN];
    __shared__ float bos[PRELEN];
    const int n = blockIdx.x, j = threadIdx.x;
    for (int idx = j; idx < NC; idx += 128) srow[idx] = g_S[n * NC + idx];
    for (int idx = j; idx < UNITS * PRELEN; idx += 128) wo[idx] = Wo[idx];
    if (j < PRELEN) bos[j] = bo[j];
    __syncthreads();
    for (int o = j; o < BATCH * PRELEN; o += 128) {
        int b = o / PRELEN, p = o - b * PRELEN;
        float acc = bos[p];
#pragma unroll
        for (int u = 0; u < UNITS; ++u) acc += srow[b * UNITS + u] * wo[u * PRELEN + p];
        out[b * (PRELEN * N_NODES) + p * N_NODES + n] = acc;
    }
}

// ---------------- launch ----------------
extern "C" void kernel_launch(void* const* d_in, const int* in_sizes, int n_in,
                              void* d_out, int out_size) {
    const float* A  = (const float*)d_in[0];
    const float* X  = (const float*)d_in[1];
    const float* st = (const float*)d_in[2];
    const float* W1 = (const float*)d_in[3];
    const float* b1 = (const float*)d_in[4];
    const float* W2 = (const float*)d_in[5];
    const float* b2 = (const float*)d_in[6];
    const float* Wo = (const float*)d_in[7];
    const float* bo = (const float*)d_in[8];
    float* out = (float*)d_out;
    (void)in_sizes; (void)n_in; (void)out_size;

    float *pAS, *pAR, *pAX, *pS, *pRS;
    __nv_bfloat16 *pAbf, *pSbf, *pRbf, *pXbf;
    cudaGetSymbolAddress((void**)&pAS, g_AS);
    cudaGetSymbolAddress((void**)&pAR, g_AR);
    cudaGetSymbolAddress((void**)&pAX, g_AX);
    cudaGetSymbolAddress((void**)&pS,  g_S);
    cudaGetSymbolAddress((void**)&pRS, g_RS);
    cudaGetSymbolAddress((void**)&pAbf, g_Abf);
    cudaGetSymbolAddress((void**)&pSbf, g_Sbf);
    cudaGetSymbolAddress((void**)&pRbf, g_Rbf);
    cudaGetSymbolAddress((void**)&pXbf, g_Xbf);

    const int DSM = 2 * 40960;   // 81920 B
    cudaFuncSetAttribute(hmma_gemm, cudaFuncAttributeMaxDynamicSharedMemorySize, DSM);

    // one-time: split A_hat and X to bf16 hi/lo; pack initial state
    split_kernel<<<(N_NODES * N_NODES + 255) / 256, 256>>>(A, pAbf, N_NODES * N_NODES, A_PART);
    split_kernel<<<(TB * N_NODES + 255) / 256, 256>>>(X, pXbf, TB * N_NODES, (size_t)TB * N_NODES);
    pack_s_kernel<<<(BATCH * N_NODES * UNITS + 255) / 256, 256>>>(st);

    // AX = A_hat @ X^T for all timesteps (ncols = 384 -> 3 N-tiles)
    hmma_gemm<<<dim3(TB / 128, N_NODES / 128), 256, DSM>>>(pAX, pAbf, pXbf, TB,
                                                           (size_t)TB * N_NODES);

    for (int t = 0; t < TSTEPS; ++t) {
        splitT_kernel<<<dim3(NC / 32, N_NODES / 32), dim3(32, 8)>>>(pS, pSbf);
        hmma_gemm<<<dim3(NC / 128, N_NODES / 128), 256, DSM>>>(pAS, pAbf, pSbf, NC,
                                                               (size_t)NC * N_NODES);
        gates1_kernel<<<dim3(2, N_NODES), 128>>>(W1, b1, t);
        splitT_kernel<<<dim3(NC / 32, N_NODES / 32), dim3(32, 8)>>>(pRS, pRbf);
        hmma_gemm<<<dim3(NC / 128, N_NODES / 128), 256, DSM>>>(pAR, pAbf, pRbf, NC,
                                                               (size_t)NC * N_NODES);
        gates2_kernel<<<dim3(2, N_NODES), 128>>>(W2, b2, t);
    }

    final_kernel<<<N_NODES, 128>>>(Wo, bo, out);
}

// round 6
// speedup vs baseline: 2.1645x; 1.0319x over previous
#include <cuda_runtime.h>
#include <cuda_bf16.h>
#include <cstdint>

// ---------------- problem constants ----------------
#define N_NODES 4096
#define UNITS   64
#define BATCH   32
#define TSTEPS  12
#define PRELEN  12
#define NC      2048                 // GEMM columns for state (b*64+u)
#define TB      384                  // t*32+b columns for X
#define A_PART  ((size_t)N_NODES * N_NODES)

// ---------------- scratch (device globals; no allocation allowed) ----------------
__device__ __align__(128) float g_S [N_NODES*NC];   // state fp32 [node][col]
__device__ __align__(128) float g_AS[N_NODES*NC];   // A @ S
__device__ __align__(128) float g_RS[N_NODES*NC];   // r * state
__device__ __align__(128) float g_AR[N_NODES*NC];   // A @ RS
__device__ __align__(128) float g_UG[N_NODES*NC];   // u gate
__device__ __align__(128) float g_AX[N_NODES*TB];   // A @ X (all steps)
__device__ __align__(128) __nv_bfloat16 g_Abf[2*A_PART];             // A hi|lo, [m][k]
__device__ __align__(128) __nv_bfloat16 g_Sbf[2*(size_t)NC*N_NODES]; // S hi|lo, [n][k]
__device__ __align__(128) __nv_bfloat16 g_Rbf[2*(size_t)NC*N_NODES]; // RS hi|lo, [n][k]
__device__ __align__(128) __nv_bfloat16 g_Xbf[2*(size_t)TB*N_NODES]; // X hi|lo, [tb][k]

// ---------------- PTX helpers (all baseline-PTX, sm_80+) ----------------
__device__ __forceinline__ uint32_t s2u(const void* p) {
    uint32_t a;
    asm("{ .reg .u64 t; cvta.to.shared.u64 t, %1; cvt.u32.u64 %0, t; }" : "=r"(a) : "l"(p));
    return a;
}
__device__ __forceinline__ void cp16(uint32_t dst, const void* src) {
    asm volatile("cp.async.cg.shared.global [%0], [%1], 16;" :: "r"(dst), "l"(src) : "memory");
}
__device__ __forceinline__ void cp_commit() {
    asm volatile("cp.async.commit_group;" ::: "memory");
}
template<int N>
__device__ __forceinline__ void cp_wait() {
    asm volatile("cp.async.wait_group %0;" :: "n"(N) : "memory");
}
__device__ __forceinline__ void ldm_x4(uint32_t* r, uint32_t a) {
    asm volatile("ldmatrix.sync.aligned.m8n8.x4.shared.b16 {%0,%1,%2,%3}, [%4];"
                 : "=r"(r[0]), "=r"(r[1]), "=r"(r[2]), "=r"(r[3]) : "r"(a));
}
__device__ __forceinline__ void mma_bf16(float* d, const uint32_t* a, const uint32_t* b) {
    asm volatile(
        "mma.sync.aligned.m16n8k16.row.col.f32.bf16.bf16.f32 "
        "{%0,%1,%2,%3}, {%4,%5,%6,%7}, {%8,%9}, {%0,%1,%2,%3};"
        : "+f"(d[0]), "+f"(d[1]), "+f"(d[2]), "+f"(d[3])
        : "r"(a[0]), "r"(a[1]), "r"(a[2]), "r"(a[3]), "r"(b[0]), "r"(b[1]));
}

// ---------------- HMMA split-GEMM ----------------
// C[m, n] = sum_k A[m,k]*B[n,k] in (emulated) fp32 via bf16 hi/lo 3 products.
// CTA tile 128x128, BK=32, 256 threads, warp tile 64x32, cp.async double buffer.
// Stage layout (bf16, row stride 40 elems = 80B): Ah[128][40] Al Bh Bl.
#define ROWB   80u        // bytes per smem row
#define ARRB   10240u     // bytes per operand array (128*80)
#define STGB   40960u     // bytes per stage
#define NKT    (N_NODES/32)

__global__ __launch_bounds__(256, 2)
void hmma_gemm(float* __restrict__ C, const __nv_bfloat16* __restrict__ Ab,
               const __nv_bfloat16* __restrict__ Bb, int ncols, size_t bPart) {
    extern __shared__ __align__(128) char smem[];
    const uint32_t sm0 = s2u(smem);

    const int tid = threadIdx.x;
    const int lane = tid & 31, wid = tid >> 5;
    const int wm = wid & 1, wn = wid >> 1;          // warp grid 2(m) x 4(n)
    const int m0 = blockIdx.y * 128;
    const int n0 = blockIdx.x * 128;

    float acc[4][4][4];
#pragma unroll
    for (int i = 0; i < 4; ++i)
#pragma unroll
        for (int j = 0; j < 4; ++j)
#pragma unroll
            for (int q = 0; q < 4; ++q) acc[i][j][q] = 0.f;

    auto load_stage = [&](int kt) {
        const uint32_t sb = sm0 + (uint32_t)(kt & 1) * STGB;
        const size_t k0 = (size_t)kt * 32;
#pragma unroll
        for (int it = 0; it < 8; ++it) {
            const int i = tid + it * 256;           // 0..2047 16B-chunks
            const int chunk = i & 3;
            const int row = (i >> 2) & 127;
            const int arr = i >> 9;                 // 0:Ah 1:Al 2:Bh 3:Bl
            const __nv_bfloat16* src =
                (arr < 2)
                    ? Ab + (size_t)arr * A_PART + (size_t)(m0 + row) * N_NODES + k0 + chunk * 8
                    : Bb + (size_t)(arr - 2) * bPart + (size_t)(n0 + row) * N_NODES + k0 + chunk * 8;
            cp16(sb + (uint32_t)arr * ARRB + (uint32_t)row * ROWB + (uint32_t)chunk * 16u, src);
        }
        cp_commit();
    };

    load_stage(0);

    // ldmatrix lane address components (computed once)
    // A (m16k16 x4): lanes 0-15 -> rows 0-15 at +0B, lanes 16-31 -> rows 0-15 at +16B
    const uint32_t aLane = (uint32_t)(lane & 15) * ROWB + (uint32_t)((lane >> 4) << 4);
    // B (two n8k16 frags per x4): lanes 0-7 rows0-7 +0B, 8-15 rows0-7 +16B,
    //                            16-23 rows8-15 +0B, 24-31 rows8-15 +16B
    const uint32_t bLane = (uint32_t)(((lane >> 4) << 3) + (lane & 7)) * ROWB
                         + (uint32_t)(((lane >> 3) & 1) << 4);

#pragma unroll 1
    for (int kt = 0; kt < NKT; ++kt) {
        if (kt + 1 < NKT) { load_stage(kt + 1); cp_wait<1>(); }
        else              { cp_wait<0>(); }
        __syncthreads();

        const uint32_t sb = sm0 + (uint32_t)(kt & 1) * STGB;
        const uint32_t aBase = sb + (uint32_t)(wm * 64) * ROWB + aLane;
        const uint32_t bBase = sb + 2u * ARRB + (uint32_t)(wn * 32) * ROWB + bLane;
#pragma unroll
        for (int ks = 0; ks < 2; ++ks) {
            const uint32_t kb = (uint32_t)(ks * 32);                      // 16 bf16 = 32B
            // B frags: one x4 covers an nf pair (hi and lo arrays)
            uint32_t bh[4][2], bl[4][2];
#pragma unroll
            for (int nf2 = 0; nf2 < 2; ++nf2) {
                const uint32_t ba = bBase + (uint32_t)(nf2 * 16) * ROWB + kb;
                uint32_t th[4], tl[4];
                ldm_x4(th, ba);
                ldm_x4(tl, ba + ARRB);
                bh[2 * nf2][0] = th[0]; bh[2 * nf2][1] = th[1];
                bh[2 * nf2 + 1][0] = th[2]; bh[2 * nf2 + 1][1] = th[3];
                bl[2 * nf2][0] = tl[0]; bl[2 * nf2][1] = tl[1];
                bl[2 * nf2 + 1][0] = tl[2]; bl[2 * nf2 + 1][1] = tl[3];
            }
#pragma unroll
            for (int mf = 0; mf < 4; ++mf) {
                const uint32_t aa = aBase + (uint32_t)(mf * 16) * ROWB + kb;
                uint32_t ah[4], al[4];
                ldm_x4(ah, aa);
                ldm_x4(al, aa + ARRB);
                // product-outer ordering: runs of 4 independent MMAs
#pragma unroll
                for (int nf = 0; nf < 4; ++nf) mma_bf16(acc[mf][nf], ah, bh[nf]);
#pragma unroll
                for (int nf = 0; nf < 4; ++nf) mma_bf16(acc[mf][nf], ah, bl[nf]);
#pragma unroll
                for (int nf = 0; nf < 4; ++nf) mma_bf16(acc[mf][nf], al, bh[nf]);
            }
        }
        __syncthreads();
    }

    // epilogue: c frag -> C.  thread holds c[row=grp][col=tl*2,+1] (r0,r1), row+8 (r2,r3)
    const int grp = lane >> 2, tl = lane & 3;
#pragma unroll
    for (int mf = 0; mf < 4; ++mf) {
#pragma unroll
        for (int nf = 0; nf < 4; ++nf) {
            const int row = m0 + wm * 64 + mf * 16 + grp;
            const int col = n0 + wn * 32 + nf * 8 + tl * 2;
            float* p0 = C + (size_t)row * ncols + col;
            p0[0] = acc[mf][nf][0]; p0[1] = acc[mf][nf][1];
            float* p1 = C + (size_t)(row + 8) * ncols + col;
            p1[0] = acc[mf][nf][2]; p1[1] = acc[mf][nf][3];
        }
    }
}

// ---------------- hi/lo split (no transpose): A_hat and X ----------------
__global__ void split_kernel(const float* __restrict__ in, __nv_bfloat16* __restrict__ out,
                             int n, size_t ps) {
    int i = blockIdx.x * blockDim.x + threadIdx.x;
    if (i < n) {
        float v = in[i];
        __nv_bfloat16 h = __float2bfloat16(v);
        out[i] = h;
        out[ps + i] = __float2bfloat16(v - __bfloat162float(h));
    }
}

// ---------------- transpose + hi/lo split: fp32 [node][col] -> bf16 [col][node] ----------------
__global__ __launch_bounds__(256)
void splitT_kernel(const float* __restrict__ in, __nv_bfloat16* __restrict__ out) {
    __shared__ float tile[32][33];
    const int col0 = blockIdx.x * 32, node0 = blockIdx.y * 32;
    const int tx = threadIdx.x, ty = threadIdx.y;
#pragma unroll
    for (int j = 0; j < 32; j += 8)
        tile[ty + j][tx] = in[(size_t)(node0 + ty + j) * NC + col0 + tx];
    __syncthreads();
#pragma unroll
    for (int j = 0; j < 32; j += 8) {
        float v = tile[tx][ty + j];
        __nv_bfloat16 h = __float2bfloat16(v);
        __nv_bfloat16 l = __float2bfloat16(v - __bfloat162float(h));
        size_t o = (size_t)(col0 + ty + j) * N_NODES + node0 + tx;
        out[o] = h;
        out[(size_t)NC * N_NODES + o] = l;
    }
}

// ---------------- input packing: state -> [node][col] fp32 ----------------
__global__ void pack_s_kernel(const float* __restrict__ st) {
    int i = blockIdx.x * blockDim.x + threadIdx.x;  // over B*N*U
    if (i < BATCH * N_NODES * UNITS) {
        int u = i & 63;
        int n = (i >> 6) & (N_NODES - 1);
        int b = i >> 18;
        g_S[n * NC + b * UNITS + u] = st[i];
    }
}

// ---------------- gate 1: v1 = sigmoid(gc1); scatter r*state -> RS, u -> UG ----------------
// TGCN chunk(2,dim=1) quirk on flattened (N,2U):
//   v1[b,n,j] is r for node 2n+(j>>6), unit j&63   when n < 2048
//   v1[b,n,j] is u for node 2(n-2048)+(j>>6)       when n >= 2048
__global__ __launch_bounds__(128)
void gates1_kernel(const float* __restrict__ W1, const float* __restrict__ b1, int t) {
    __shared__ float asr[16][64];
    __shared__ float axs[16];
    const int j  = threadIdx.x;          // 0..127 output feature
    const int n  = blockIdx.y;           // v1 node
    const int b0 = blockIdx.x * 16;      // batch block
    float w[65];
#pragma unroll
    for (int f = 0; f < 65; ++f) w[f] = W1[f * 128 + j];
    const float bias = b1[j];

    const float* src = g_AS + n * NC + b0 * UNITS;
    for (int idx = j; idx < 1024; idx += 128) ((float*)asr)[idx] = src[idx];
    if (j < 16) axs[j] = g_AX[n * TB + t * BATCH + b0 + j];
    __syncthreads();

    const int jh = j >> 6, u2 = j & 63;
    for (int p = 0; p < 16; ++p) {
        float acc = bias + axs[p] * w[0];
#pragma unroll
        for (int u = 0; u < 64; ++u) acc += asr[p][u] * w[u + 1];
        float sg = 1.f / (1.f + __expf(-acc));
        const int b = b0 + p;
        if (n < 2048) {
            const int idx = (2 * n + jh) * NC + b * UNITS + u2;
            g_RS[idx] = sg * g_S[idx];
        } else {
            g_UG[(2 * (n - 2048) + jh) * NC + b * UNITS + u2] = sg;
        }
    }
}

// ---------------- gate 2: c = tanh(gc2); state = u*state + (1-u)*c ----------------
__global__ __launch_bounds__(128)
void gates2_kernel(const float* __restrict__ W2, const float* __restrict__ b2, int t) {
    __shared__ float arr[16][64];
    __shared__ float axs[16];
    const int j  = threadIdx.x;
    const int n  = blockIdx.y;           // real node
    const int b0 = blockIdx.x * 16;
    const int u2 = j & 63, ph = j >> 6;
    float w[65];
#pragma unroll
    for (int f = 0; f < 65; ++f) w[f] = W2[f * 64 + u2];
    const float bias = b2[u2];

    const float* src = g_AR + n * NC + b0 * UNITS;
    for (int idx = j; idx < 1024; idx += 128) ((float*)arr)[idx] = src[idx];
    if (j < 16) axs[j] = g_AX[n * TB + t * BATCH + b0 + j];
    __syncthreads();

    for (int pp = 0; pp < 8; ++pp) {
        const int p = pp * 2 + ph;
        const int b = b0 + p;
        float acc = bias + axs[p] * w[0];
#pragma unroll
        for (int u = 0; u < 64; ++u) acc += arr[p][u] * w[u + 1];
        float c = tanhf(acc);
        const int idx = n * NC + b * UNITS + u2;
        const float ug = g_UG[idx];
        g_S[idx] = ug * g_S[idx] + (1.f - ug) * c;
    }
}

// ---------------- output head: out[b,p,n] = state[b,n,:] @ Wo + bo ----------------
__global__ __launch_bounds__(128)
void final_kernel(const float* __restrict__ Wo, const float* __restrict__ bo,
                  float* __restrict__ out) {
    __shared__ float srow[NC];
    __shared__ float wo[UNITS * PRELEN];
    __shared__ float bos[PRELEN];
    const int n = blockIdx.x, j = threadIdx.x;
    for (int idx = j; idx < NC; idx += 128) srow[idx] = g_S[n * NC + idx];
    for (int idx = j; idx < UNITS * PRELEN; idx += 128) wo[idx] = Wo[idx];
    if (j < PRELEN) bos[j] = bo[j];
    __syncthreads();
    for (int o = j; o < BATCH * PRELEN; o += 128) {
        int b = o / PRELEN, p = o - b * PRELEN;
        float acc = bos[p];
#pragma unroll
        for (int u = 0; u < UNITS; ++u) acc += srow[b * UNITS + u] * wo[u * PRELEN + p];
        out[b * (PRELEN * N_NODES) + p * N_NODES + n] = acc;
    }
}

// ---------------- launch ----------------
extern "C" void kernel_launch(void* const* d_in, const int* in_sizes, int n_in,
                              void* d_out, int out_size) {
    const float* A  = (const float*)d_in[0];
    const float* X  = (const float*)d_in[1];
    const float* st = (const float*)d_in[2];
    const float* W1 = (const float*)d_in[3];
    const float* b1 = (const float*)d_in[4];
    const float* W2 = (const float*)d_in[5];
    const float* b2 = (const float*)d_in[6];
    const float* Wo = (const float*)d_in[7];
    const float* bo = (const float*)d_in[8];
    float* out = (float*)d_out;
    (void)in_sizes; (void)n_in; (void)out_size;

    float *pAS, *pAR, *pAX, *pS, *pRS;
    __nv_bfloat16 *pAbf, *pSbf, *pRbf, *pXbf;
    cudaGetSymbolAddress((void**)&pAS, g_AS);
    cudaGetSymbolAddress((void**)&pAR, g_AR);
    cudaGetSymbolAddress((void**)&pAX, g_AX);
    cudaGetSymbolAddress((void**)&pS,  g_S);
    cudaGetSymbolAddress((void**)&pRS, g_RS);
    cudaGetSymbolAddress((void**)&pAbf, g_Abf);
    cudaGetSymbolAddress((void**)&pSbf, g_Sbf);
    cudaGetSymbolAddress((void**)&pRbf, g_Rbf);
    cudaGetSymbolAddress((void**)&pXbf, g_Xbf);

    const int DSM = 2 * 40960;   // 81920 B
    cudaFuncSetAttribute(hmma_gemm, cudaFuncAttributeMaxDynamicSharedMemorySize, DSM);

    // one-time: split A_hat and X to bf16 hi/lo; pack initial state
    split_kernel<<<(N_NODES * N_NODES + 255) / 256, 256>>>(A, pAbf, N_NODES * N_NODES, A_PART);
    split_kernel<<<(TB * N_NODES + 255) / 256, 256>>>(X, pXbf, TB * N_NODES, (size_t)TB * N_NODES);
    pack_s_kernel<<<(BATCH * N_NODES * UNITS + 255) / 256, 256>>>(st);

    // AX = A_hat @ X^T for all timesteps (ncols = 384 -> 3 N-tiles)
    hmma_gemm<<<dim3(TB / 128, N_NODES / 128), 256, DSM>>>(pAX, pAbf, pXbf, TB,
                                                           (size_t)TB * N_NODES);

    for (int t = 0; t < TSTEPS; ++t) {
        splitT_kernel<<<dim3(NC / 32, N_NODES / 32), dim3(32, 8)>>>(pS, pSbf);
        hmma_gemm<<<dim3(NC / 128, N_NODES / 128), 256, DSM>>>(pAS, pAbf, pSbf, NC,
                                                               (size_t)NC * N_NODES);
        gates1_kernel<<<dim3(2, N_NODES), 128>>>(W1, b1, t);
        splitT_kernel<<<dim3(NC / 32, N_NODES / 32), dim3(32, 8)>>>(pRS, pRbf);
        hmma_gemm<<<dim3(NC / 128, N_NODES / 128), 256, DSM>>>(pAR, pAbf, pRbf, NC,
                                                               (size_t)NC * N_NODES);
        gates2_kernel<<<dim3(2, N_NODES), 128>>>(W2, b2, t);
    }

    final_kernel<<<N_NODES, 128>>>(Wo, bo, out);
}

// round 7
// speedup vs baseline: 2.2483x; 1.0387x over previous
#include <cuda_runtime.h>
#include <cuda_bf16.h>
#include <cstdint>

// ---------------- problem constants ----------------
#define N_NODES 4096
#define UNITS   64
#define BATCH   32
#define TSTEPS  12
#define PRELEN  12
#define NC      2048                 // GEMM columns for state (b*64+u)
#define TB      384                  // t*32+b columns for X
#define A_PART  ((size_t)N_NODES * N_NODES)

// ---------------- scratch (device globals; no allocation allowed) ----------------
__device__ __align__(128) float g_S [N_NODES*NC];   // state fp32 [node][col]
__device__ __align__(128) float g_AS[N_NODES*NC];   // A @ S
__device__ __align__(128) float g_RS[N_NODES*NC];   // r * state
__device__ __align__(128) float g_AR[N_NODES*NC];   // A @ RS
__device__ __align__(128) float g_UG[N_NODES*NC];   // u gate
__device__ __align__(128) float g_AX[N_NODES*TB];   // A @ X (all steps)
__device__ __align__(128) __nv_bfloat16 g_Abf[2*A_PART];             // A hi|lo, [m][k]
__device__ __align__(128) __nv_bfloat16 g_Sbf[2*(size_t)NC*N_NODES]; // S hi|lo, [n][k]
__device__ __align__(128) __nv_bfloat16 g_Rbf[2*(size_t)NC*N_NODES]; // RS hi|lo, [n][k]
__device__ __align__(128) __nv_bfloat16 g_Xbf[2*(size_t)TB*N_NODES]; // X hi|lo, [tb][k]

// ---------------- PTX helpers (all baseline-PTX, sm_80+) ----------------
__device__ __forceinline__ uint32_t s2u(const void* p) {
    uint32_t a;
    asm("{ .reg .u64 t; cvta.to.shared.u64 t, %1; cvt.u32.u64 %0, t; }" : "=r"(a) : "l"(p));
    return a;
}
__device__ __forceinline__ void cp16(uint32_t dst, const void* src) {
    asm volatile("cp.async.cg.shared.global [%0], [%1], 16;" :: "r"(dst), "l"(src) : "memory");
}
__device__ __forceinline__ void cp_commit() {
    asm volatile("cp.async.commit_group;" ::: "memory");
}
template<int N>
__device__ __forceinline__ void cp_wait() {
    asm volatile("cp.async.wait_group %0;" :: "n"(N) : "memory");
}
__device__ __forceinline__ void ldm_x4(uint32_t* r, uint32_t a) {
    asm volatile("ldmatrix.sync.aligned.m8n8.x4.shared.b16 {%0,%1,%2,%3}, [%4];"
                 : "=r"(r[0]), "=r"(r[1]), "=r"(r[2]), "=r"(r[3]) : "r"(a));
}
__device__ __forceinline__ void mma_bf16(float* d, const uint32_t* a, const uint32_t* b) {
    asm volatile(
        "mma.sync.aligned.m16n8k16.row.col.f32.bf16.bf16.f32 "
        "{%0,%1,%2,%3}, {%4,%5,%6,%7}, {%8,%9}, {%0,%1,%2,%3};"
        : "+f"(d[0]), "+f"(d[1]), "+f"(d[2]), "+f"(d[3])
        : "r"(a[0]), "r"(a[1]), "r"(a[2]), "r"(a[3]), "r"(b[0]), "r"(b[1]));
}

// ---------------- HMMA split-GEMM ----------------
// C[m, n] = sum_k A[m,k]*B[n,k], fp32 via bf16 hi/lo 3 products.
// CTA tile 256x128, BK=32, 512 threads (warp grid 4m x 4n, warp tile 64x32),
// 3-stage cp.async pipeline, ONE __syncthreads per k-tile.
// Stage layout (80B rows): Ah[256] | Al[256] | Bh[128] | Bl[128]  = 61440 B.
#define ROWB   80u
#define AH_OFF 0u
#define AL_OFF 20480u
#define BH_OFF 40960u
#define BL_OFF 51200u
#define STGB   61440u
#define NKT    (N_NODES/32)

__global__ __launch_bounds__(512, 1)
void hmma_gemm(float* __restrict__ C, const __nv_bfloat16* __restrict__ Ab,
               const __nv_bfloat16* __restrict__ Bb, int ncols, size_t bPart) {
    extern __shared__ __align__(128) char smem[];
    const uint32_t sm0 = s2u(smem);

    const int tid = threadIdx.x;
    const int lane = tid & 31, wid = tid >> 5;
    const int wm = wid & 3, wn = wid >> 2;          // warp grid 4(m) x 4(n)
    const int m0 = blockIdx.y * 256;
    const int n0 = blockIdx.x * 128;

    float acc[4][4][4];
#pragma unroll
    for (int i = 0; i < 4; ++i)
#pragma unroll
        for (int j = 0; j < 4; ++j)
#pragma unroll
            for (int q = 0; q < 4; ++q) acc[i][j][q] = 0.f;

    auto load_stage = [&](int kt) {
        const uint32_t sb = sm0 + (uint32_t)(kt % 3) * STGB;
        const size_t k0 = (size_t)kt * 32;
#pragma unroll
        for (int it = 0; it < 6; ++it) {
            const int i = tid + it * 512;           // 0..3071 16B-chunks
            const int chunk = i & 3;
            const int row = i >> 2;                 // 0..767
            const __nv_bfloat16* src;
            uint32_t rel;
            if (row < 512) {                        // A: hi rows 0-255, lo rows 256-511
                const int part = row >> 8, m = row & 255;
                src = Ab + (size_t)part * A_PART + (size_t)(m0 + m) * N_NODES + k0;
                rel = (uint32_t)part * AL_OFF + (uint32_t)m * ROWB;
            } else {                                // B: hi rows 512-639, lo 640-767
                const int r = row - 512;
                const int part = r >> 7, n = r & 127;
                src = Bb + (size_t)part * bPart + (size_t)(n0 + n) * N_NODES + k0;
                rel = BH_OFF + (uint32_t)part * 10240u + (uint32_t)n * ROWB;
            }
            cp16(sb + rel + (uint32_t)chunk * 16u, src + chunk * 8);
        }
        cp_commit();
    };

    load_stage(0);
    load_stage(1);

    // ldmatrix lane address components
    const uint32_t aLane = (uint32_t)(lane & 15) * ROWB + (uint32_t)((lane >> 4) << 4);
    const uint32_t bLane = (uint32_t)(((lane >> 4) << 3) + (lane & 7)) * ROWB
                         + (uint32_t)(((lane >> 3) & 1) << 4);

#pragma unroll 1
    for (int kt = 0; kt < NKT; ++kt) {
        if (kt < NKT - 1) cp_wait<1>();  // FIFO completion -> stage kt ready
        else              cp_wait<0>();
        __syncthreads();
        if (kt + 2 < NKT) load_stage(kt + 2);   // safe: buffer (kt+2)%3 free post-sync

        const uint32_t sb = sm0 + (uint32_t)(kt % 3) * STGB;
        const uint32_t aBase = sb + (uint32_t)(wm * 64) * ROWB + aLane;
        const uint32_t bBase = sb + BH_OFF + (uint32_t)(wn * 32) * ROWB + bLane;
#pragma unroll
        for (int ks = 0; ks < 2; ++ks) {
            const uint32_t kb = (uint32_t)(ks * 32);      // 16 bf16 = 32B
            uint32_t bh[4][2], bl[4][2];
#pragma unroll
            for (int nf2 = 0; nf2 < 2; ++nf2) {
                const uint32_t ba = bBase + (uint32_t)(nf2 * 16) * ROWB + kb;
                uint32_t th[4], tl[4];
                ldm_x4(th, ba);
                ldm_x4(tl, ba + (BL_OFF - BH_OFF));
                bh[2 * nf2][0] = th[0]; bh[2 * nf2][1] = th[1];
                bh[2 * nf2 + 1][0] = th[2]; bh[2 * nf2 + 1][1] = th[3];
                bl[2 * nf2][0] = tl[0]; bl[2 * nf2][1] = tl[1];
                bl[2 * nf2 + 1][0] = tl[2]; bl[2 * nf2 + 1][1] = tl[3];
            }
#pragma unroll
            for (int mf = 0; mf < 4; ++mf) {
                const uint32_t aa = aBase + (uint32_t)(mf * 16) * ROWB + kb;
                uint32_t ah[4], al[4];
                ldm_x4(ah, aa);
                ldm_x4(al, aa + AL_OFF);
#pragma unroll
                for (int nf = 0; nf < 4; ++nf) mma_bf16(acc[mf][nf], ah, bh[nf]);
#pragma unroll
                for (int nf = 0; nf < 4; ++nf) mma_bf16(acc[mf][nf], ah, bl[nf]);
#pragma unroll
                for (int nf = 0; nf < 4; ++nf) mma_bf16(acc[mf][nf], al, bh[nf]);
            }
        }
    }

    // epilogue
    const int grp = lane >> 2, tl = lane & 3;
#pragma unroll
    for (int mf = 0; mf < 4; ++mf) {
#pragma unroll
        for (int nf = 0; nf < 4; ++nf) {
            const int row = m0 + wm * 64 + mf * 16 + grp;
            const int col = n0 + wn * 32 + nf * 8 + tl * 2;
            float* p0 = C + (size_t)row * ncols + col;
            p0[0] = acc[mf][nf][0]; p0[1] = acc[mf][nf][1];
            float* p1 = C + (size_t)(row + 8) * ncols + col;
            p1[0] = acc[mf][nf][2]; p1[1] = acc[mf][nf][3];
        }
    }
}

// ---------------- hi/lo split (no transpose): A_hat and X ----------------
__global__ void split_kernel(const float* __restrict__ in, __nv_bfloat16* __restrict__ out,
                             int n, size_t ps) {
    int i = blockIdx.x * blockDim.x + threadIdx.x;
    if (i < n) {
        float v = in[i];
        __nv_bfloat16 h = __float2bfloat16(v);
        out[i] = h;
        out[ps + i] = __float2bfloat16(v - __bfloat162float(h));
    }
}

// ---------------- transpose + hi/lo split: fp32 [node][col] -> bf16 [col][node] ----------------
__global__ __launch_bounds__(256)
void splitT_kernel(const float* __restrict__ in, __nv_bfloat16* __restrict__ out) {
    __shared__ float tile[32][33];
    const int col0 = blockIdx.x * 32, node0 = blockIdx.y * 32;
    const int tx = threadIdx.x, ty = threadIdx.y;
#pragma unroll
    for (int j = 0; j < 32; j += 8)
        tile[ty + j][tx] = in[(size_t)(node0 + ty + j) * NC + col0 + tx];
    __syncthreads();
#pragma unroll
    for (int j = 0; j < 32; j += 8) {
        float v = tile[tx][ty + j];
        __nv_bfloat16 h = __float2bfloat16(v);
        __nv_bfloat16 l = __float2bfloat16(v - __bfloat162float(h));
        size_t o = (size_t)(col0 + ty + j) * N_NODES + node0 + tx;
        out[o] = h;
        out[(size_t)NC * N_NODES + o] = l;
    }
}

// ---------------- input packing: state -> [node][col] fp32 ----------------
__global__ void pack_s_kernel(const float* __restrict__ st) {
    int i = blockIdx.x * blockDim.x + threadIdx.x;  // over B*N*U
    if (i < BATCH * N_NODES * UNITS) {
        int u = i & 63;
        int n = (i >> 6) & (N_NODES - 1);
        int b = i >> 18;
        g_S[n * NC + b * UNITS + u] = st[i];
    }
}

// ---------------- gate 1: v1 = sigmoid(gc1); scatter r*state -> RS, u -> UG ----------------
// TGCN chunk(2,dim=1) quirk on flattened (N,2U):
//   v1[b,n,j] is r for node 2n+(j>>6), unit j&63   when n < 2048
//   v1[b,n,j] is u for node 2(n-2048)+(j>>6)       when n >= 2048
__global__ __launch_bounds__(128)
void gates1_kernel(const float* __restrict__ W1, const float* __restrict__ b1, int t) {
    __shared__ __align__(16) float asr[16][64];
    __shared__ float axs[16];
    const int j  = threadIdx.x;          // 0..127 output feature
    const int n  = blockIdx.y;           // v1 node
    const int b0 = blockIdx.x * 16;      // batch block
    float w[65];
#pragma unroll
    for (int f = 0; f < 65; ++f) w[f] = W1[f * 128 + j];
    const float bias = b1[j];

    const float* src = g_AS + n * NC + b0 * UNITS;
    for (int idx = j; idx < 1024; idx += 128) ((float*)asr)[idx] = src[idx];
    if (j < 16) axs[j] = g_AX[n * TB + t * BATCH + b0 + j];
    __syncthreads();

    const int jh = j >> 6, u2 = j & 63;
    for (int p = 0; p < 16; ++p) {
        float acc = bias + axs[p] * w[0];
        const float4* ap4 = (const float4*)asr[p];
#pragma unroll
        for (int q = 0; q < 16; ++q) {
            float4 v = ap4[q];
            acc += v.x * w[4 * q + 1] + v.y * w[4 * q + 2]
                 + v.z * w[4 * q + 3] + v.w * w[4 * q + 4];
        }
        float sg = 1.f / (1.f + __expf(-acc));
        const int b = b0 + p;
        if (n < 2048) {
            const int idx = (2 * n + jh) * NC + b * UNITS + u2;
            g_RS[idx] = sg * g_S[idx];
        } else {
            g_UG[(2 * (n - 2048) + jh) * NC + b * UNITS + u2] = sg;
        }
    }
}

// ---------------- gate 2: c = tanh(gc2); state = u*state + (1-u)*c ----------------
__global__ __launch_bounds__(128)
void gates2_kernel(const float* __restrict__ W2, const float* __restrict__ b2, int t) {
    __shared__ __align__(16) float arr[16][64];
    __shared__ float axs[16];
    const int j  = threadIdx.x;
    const int n  = blockIdx.y;           // real node
    const int b0 = blockIdx.x * 16;
    const int u2 = j & 63, ph = j >> 6;
    float w[65];
#pragma unroll
    for (int f = 0; f < 65; ++f) w[f] = W2[f * 64 + u2];
    const float bias = b2[u2];

    const float* src = g_AR + n * NC + b0 * UNITS;
    for (int idx = j; idx < 1024; idx += 128) ((float*)arr)[idx] = src[idx];
    if (j < 16) axs[j] = g_AX[n * TB + t * BATCH + b0 + j];
    __syncthreads();

    for (int pp = 0; pp < 8; ++pp) {
        const int p = pp * 2 + ph;
        const int b = b0 + p;
        float acc = bias + axs[p] * w[0];
        const float4* ap4 = (const float4*)arr[p];
#pragma unroll
        for (int q = 0; q < 16; ++q) {
            float4 v = ap4[q];
            acc += v.x * w[4 * q + 1] + v.y * w[4 * q + 2]
                 + v.z * w[4 * q + 3] + v.w * w[4 * q + 4];
        }
        float c = tanhf(acc);
        const int idx = n * NC + b * UNITS + u2;
        const float ug = g_UG[idx];
        g_S[idx] = ug * g_S[idx] + (1.f - ug) * c;
    }
}

// ---------------- output head: out[b,p,n] = state[b,n,:] @ Wo + bo ----------------
__global__ __launch_bounds__(128)
void final_kernel(const float* __restrict__ Wo, const float* __restrict__ bo,
                  float* __restrict__ out) {
    __shared__ float srow[NC];
    __shared__ float wo[UNITS * PRELEN];
    __shared__ float bos[PRELEN];
    const int n = blockIdx.x, j = threadIdx.x;
    for (int idx = j; idx < NC; idx += 128) srow[idx] = g_S[n * NC + idx];
    for (int idx = j; idx < UNITS * PRELEN; idx += 128) wo[idx] = Wo[idx];
    if (j < PRELEN) bos[j] = bo[j];
    __syncthreads();
    for (int o = j; o < BATCH * PRELEN; o += 128) {
        int b = o / PRELEN, p = o - b * PRELEN;
        float acc = bos[p];
#pragma unroll
        for (int u = 0; u < UNITS; ++u) acc += srow[b * UNITS + u] * wo[u * PRELEN + p];
        out[b * (PRELEN * N_NODES) + p * N_NODES + n] = acc;
    }
}

// ---------------- launch ----------------
extern "C" void kernel_launch(void* const* d_in, const int* in_sizes, int n_in,
                              void* d_out, int out_size) {
    const float* A  = (const float*)d_in[0];
    const float* X  = (const float*)d_in[1];
    const float* st = (const float*)d_in[2];
    const float* W1 = (const float*)d_in[3];
    const float* b1 = (const float*)d_in[4];
    const float* W2 = (const float*)d_in[5];
    const float* b2 = (const float*)d_in[6];
    const float* Wo = (const float*)d_in[7];
    const float* bo = (const float*)d_in[8];
    float* out = (float*)d_out;
    (void)in_sizes; (void)n_in; (void)out_size;

    float *pAS, *pAR, *pAX, *pS, *pRS;
    __nv_bfloat16 *pAbf, *pSbf, *pRbf, *pXbf;
    cudaGetSymbolAddress((void**)&pAS, g_AS);
    cudaGetSymbolAddress((void**)&pAR, g_AR);
    cudaGetSymbolAddress((void**)&pAX, g_AX);
    cudaGetSymbolAddress((void**)&pS,  g_S);
    cudaGetSymbolAddress((void**)&pRS, g_RS);
    cudaGetSymbolAddress((void**)&pAbf, g_Abf);
    cudaGetSymbolAddress((void**)&pSbf, g_Sbf);
    cudaGetSymbolAddress((void**)&pRbf, g_Rbf);
    cudaGetSymbolAddress((void**)&pXbf, g_Xbf);

    const int DSM = 3 * 61440;   // 184320 B
    cudaFuncSetAttribute(hmma_gemm, cudaFuncAttributeMaxDynamicSharedMemorySize, DSM);

    // one-time: split A_hat and X to bf16 hi/lo; pack initial state
    split_kernel<<<(N_NODES * N_NODES + 255) / 256, 256>>>(A, pAbf, N_NODES * N_NODES, A_PART);
    split_kernel<<<(TB * N_NODES + 255) / 256, 256>>>(X, pXbf, TB * N_NODES, (size_t)TB * N_NODES);
    pack_s_kernel<<<(BATCH * N_NODES * UNITS + 255) / 256, 256>>>(st);

    // AX = A_hat @ X^T for all timesteps
    hmma_gemm<<<dim3(TB / 128, N_NODES / 256), 512, DSM>>>(pAX, pAbf, pXbf, TB,
                                                           (size_t)TB * N_NODES);

    for (int t = 0; t < TSTEPS; ++t) {
        splitT_kernel<<<dim3(NC / 32, N_NODES / 32), dim3(32, 8)>>>(pS, pSbf);
        hmma_gemm<<<dim3(NC / 128, N_NODES / 256), 512, DSM>>>(pAS, pAbf, pSbf, NC,
                                                               (size_t)NC * N_NODES);
        gates1_kernel<<<dim3(2, N_NODES), 128>>>(W1, b1, t);
        splitT_kernel<<<dim3(NC / 32, N_NODES / 32), dim3(32, 8)>>>(pRS, pRbf);
        hmma_gemm<<<dim3(NC / 128, N_NODES / 256), 512, DSM>>>(pAR, pAbf, pRbf, NC,
                                                               (size_t)NC * N_NODES);
        gates2_kernel<<<dim3(2, N_NODES), 128>>>(W2, b2, t);
    }

    final_kernel<<<N_NODES, 128>>>(Wo, bo, out);
}